// round 1
// baseline (speedup 1.0000x reference)
#include <cuda_runtime.h>
#include <float.h>

// VectorQuantize: z[16,256,32,32] f32, codebook[8192,256] f32
// -> zq[16,256,32,32] f32 (gathered nearest codebook rows), idx[16,32,32]
// Output buffer: zq flattened (4194304 f32) then idx as f32 (16384) if room.

#define NPTS   16384       // 16*32*32
#define NC     256
#define NK     8192
#define NSPLIT 8
#define KSPLIT (NK / NSPLIT)   // 1024 codes per split
#define BM     128
#define BN     128
#define BK     16
#define ZQ_ELEMS (16 * 256 * 32 * 32)  // 4194304

// ---- scratch (no cudaMalloc allowed) ----
__device__ float g_zf[NPTS * NC];      // z transposed to [n][c]
__device__ float g_c2[NK * NC];        // -2 * codebook (matches reference's -2.0*cb.T)
__device__ float g_cn[NK];             // |cb_k|^2
__device__ float g_zn[NPTS];           // |z_n|^2
__device__ float g_pval[NSPLIT * NPTS];
__device__ int   g_pidx[NSPLIT * NPTS];
__device__ int   g_idx[NPTS];

// ---------------- prep: codebook -> -2*cb and |cb|^2 ----------------
__global__ void prep_cb(const float* __restrict__ cb) {
    int k = blockIdx.x;
    int t = threadIdx.x;
    float v = cb[k * NC + t];
    g_c2[k * NC + t] = -2.0f * v;
    __shared__ float red[256];
    red[t] = v * v;
    __syncthreads();
    for (int s = 128; s > 0; s >>= 1) {
        if (t < s) red[t] += red[t + s];
        __syncthreads();
    }
    if (t == 0) g_cn[k] = red[0];
}

// ---------------- prep: z -> zf[n][c] and |z_n|^2 ----------------
__global__ void prep_z(const float* __restrict__ z) {
    int n = blockIdx.x * blockDim.x + threadIdx.x;   // 0..16383
    int b  = n >> 10;          // /1024
    int hw = n & 1023;
    const float* zp = z + (size_t)b * (NC * 1024) + hw;
    float acc = 0.f;
#pragma unroll 8
    for (int c = 0; c < NC; c++) {
        float v = zp[(size_t)c * 1024];
        g_zf[n * NC + c] = v;
        acc += v * v;
    }
    g_zn[n] = acc;
}

// ---------------- main: fused SGEMM (z @ (-2 cb^T)) + argmin ----------------
__global__ __launch_bounds__(256, 2) void vq_main() {
    __shared__ float As[BK][BM + 4];
    __shared__ float Bs[BK][BN + 4];
    __shared__ float sval[BM][16];
    __shared__ int   sidx[BM][16];

    const int t  = threadIdx.x;
    const int tx = t & 15;       // col group (8 cols each, contiguous)
    const int ty = t >> 4;       // row group (8 rows each, contiguous)
    const int row0  = blockIdx.y * BM;
    const int split = blockIdx.x;
    const int kbase = split * KSPLIT;

    float best[8];
    int   bidx[8];
#pragma unroll
    for (int i = 0; i < 8; i++) { best[i] = FLT_MAX; bidx[i] = 0; }

    float zn[8];
#pragma unroll
    for (int i = 0; i < 8; i++) zn[i] = g_zn[row0 + ty * 8 + i];

    for (int nt = 0; nt < KSPLIT / BN; nt++) {
        const int code0 = kbase + nt * BN;
        float acc[8][8];
#pragma unroll
        for (int i = 0; i < 8; i++)
#pragma unroll
            for (int j = 0; j < 8; j++) acc[i][j] = 0.f;

        for (int kc = 0; kc < NC / BK; kc++) {
            // fill As (z rows) and Bs (code rows), transposed to [k][m]
#pragma unroll
            for (int ld = 0; ld < 2; ld++) {
                int e   = t + ld * 256;
                int row = e >> 2;            // 0..127
                int cq  = (e & 3) * 4;       // 0,4,8,12
                float4 va = *(const float4*)&g_zf[(size_t)(row0 + row) * NC + kc * BK + cq];
                As[cq + 0][row] = va.x; As[cq + 1][row] = va.y;
                As[cq + 2][row] = va.z; As[cq + 3][row] = va.w;
                float4 vb = *(const float4*)&g_c2[(size_t)(code0 + row) * NC + kc * BK + cq];
                Bs[cq + 0][row] = vb.x; Bs[cq + 1][row] = vb.y;
                Bs[cq + 2][row] = vb.z; Bs[cq + 3][row] = vb.w;
            }
            __syncthreads();
#pragma unroll
            for (int k = 0; k < BK; k++) {
                float a[8], b[8];
                *(float4*)&a[0] = *(const float4*)&As[k][ty * 8];
                *(float4*)&a[4] = *(const float4*)&As[k][ty * 8 + 4];
                *(float4*)&b[0] = *(const float4*)&Bs[k][tx * 8];
                *(float4*)&b[4] = *(const float4*)&Bs[k][tx * 8 + 4];
#pragma unroll
                for (int i = 0; i < 8; i++)
#pragma unroll
                    for (int j = 0; j < 8; j++)
                        acc[i][j] = fmaf(a[i], b[j], acc[i][j]);
            }
            __syncthreads();
        }

        // epilogue: dist = (dot2 + |z|^2) + |cb|^2 (same add order as reference)
        float cn[8];
#pragma unroll
        for (int j = 0; j < 8; j++) cn[j] = g_cn[code0 + tx * 8 + j];
#pragma unroll
        for (int i = 0; i < 8; i++) {
#pragma unroll
            for (int j = 0; j < 8; j++) {   // j ascending => first-min tie-break
                float s = (acc[i][j] + zn[i]) + cn[j];
                if (s < best[i]) { best[i] = s; bidx[i] = code0 + tx * 8 + j; }
            }
        }
    }

    // block reduction across the 16 col-groups (prefer smaller idx on ties)
#pragma unroll
    for (int i = 0; i < 8; i++) {
        sval[ty * 8 + i][tx] = best[i];
        sidx[ty * 8 + i][tx] = bidx[i];
    }
    __syncthreads();
    if (t < BM) {
        float bv = sval[t][0];
        int   bi = sidx[t][0];
#pragma unroll
        for (int x = 1; x < 16; x++) {
            float v = sval[t][x];
            int  ix = sidx[t][x];
            if (v < bv || (v == bv && ix < bi)) { bv = v; bi = ix; }
        }
        g_pval[split * NPTS + row0 + t] = bv;
        g_pidx[split * NPTS + row0 + t] = bi;
    }
}

// ---------------- combine split-K partial argmins ----------------
__global__ void vq_combine() {
    int n = blockIdx.x * blockDim.x + threadIdx.x;
    float bv = g_pval[n];
    int   bi = g_pidx[n];
#pragma unroll
    for (int s = 1; s < NSPLIT; s++) {     // ascending split == ascending code idx
        float v = g_pval[s * NPTS + n];
        int  ix = g_pidx[s * NPTS + n];
        if (v < bv || (v == bv && ix < bi)) { bv = v; bi = ix; }
    }
    g_idx[n] = bi;
}

// ---------------- gather: zq[b][c][h][w] = cb[idx[n]][c] ----------------
__global__ void vq_gather(const float* __restrict__ cb, float* __restrict__ out) {
    int o = blockIdx.x * blockDim.x + threadIdx.x;   // 0..4194303
    int w = o & 31;
    int h = (o >> 5) & 31;
    int c = (o >> 10) & 255;
    int b = o >> 18;
    int n = (b << 10) + (h << 5) + w;
    out[o] = cb[(size_t)g_idx[n] * NC + c];
}

__global__ void vq_idx_out(float* __restrict__ out) {
    int n = blockIdx.x * blockDim.x + threadIdx.x;
    out[ZQ_ELEMS + n] = (float)g_idx[n];
}

extern "C" void kernel_launch(void* const* d_in, const int* in_sizes, int n_in,
                              void* d_out, int out_size) {
    const float* z  = (const float*)d_in[0];
    const float* cb = (const float*)d_in[1];
    // guard against input-order surprises
    if (n_in >= 2 && in_sizes[0] == NK * NC && in_sizes[1] == NPTS * NC) {
        const float* tmp = z; z = cb; cb = tmp;
    }
    float* out = (float*)d_out;

    prep_cb<<<NK, 256>>>(cb);
    prep_z<<<NPTS / 256, 256>>>(z);
    vq_main<<<dim3(NSPLIT, NPTS / BM), 256>>>();
    vq_combine<<<NPTS / 256, 256>>>();
    vq_gather<<<ZQ_ELEMS / 256, 256>>>(cb, out);
    if (out_size >= ZQ_ELEMS + NPTS)
        vq_idx_out<<<NPTS / 256, 256>>>(out);
}

// round 3
// speedup vs baseline: 3.5489x; 3.5489x over previous
#include <cuda_runtime.h>
#include <cuda_bf16.h>
#include <float.h>
#include <stdint.h>

// VectorQuantize: z[16,256,32,32] f32, codebook[8192,256] f32
// out: zq[16,256,32,32] f32 (+ idx tail as f32)
// coarse bf16 mma.sync GEMM -> bf16 scores -> margin candidates -> exact fp32 refine.

#define NPTS 16384
#define NC   256
#define NK   8192
#define ZQ_ELEMS 4194304
#define TM 128
#define TN 128
#define MARGIN 8e-3f

// ---------------- scratch ----------------
__device__ unsigned short g_ah[NPTS * NC];    // bf16(z)
__device__ unsigned short g_bh[NK * NC];      // bf16(-2cb)
__device__ float g_zf[NPTS * NC];             // fp32 z rows (refine)
__device__ float g_zn[NPTS];
__device__ float g_cn[NK];                    // |cb|^2 fp32
__device__ unsigned short g_dist[(size_t)NPTS * NK];  // coarse scores bf16 (256MB)
__device__ int g_idx[NPTS];

// ---------------- PTX helpers (base PTX only; no 'a' features) ----------------
__device__ __forceinline__ uint32_t smem_u32(const void* p) {
    uint32_t a;
    asm("{ .reg .u64 t; cvta.to.shared.u64 t, %1; cvt.u32.u64 %0, t; }" : "=r"(a) : "l"(p));
    return a;
}

#define CP_ASYNC16(sm, gp) \
    asm volatile("cp.async.cg.shared.global [%0], [%1], 16;" :: "r"(sm), "l"(gp) : "memory")
#define CP_COMMIT() asm volatile("cp.async.commit_group;" ::: "memory")
#define CP_WAIT(n)  asm volatile("cp.async.wait_group %0;" :: "n"(n) : "memory")

#define LDSM_X4(r0, r1, r2, r3, ad) \
    asm volatile("ldmatrix.sync.aligned.m8n8.x4.shared.b16 {%0,%1,%2,%3}, [%4];" \
                 : "=r"(r0), "=r"(r1), "=r"(r2), "=r"(r3) : "r"(ad))

#define MMA16816(d, a0, a1, a2, a3, b0, b1) \
    asm volatile("mma.sync.aligned.m16n8k16.row.col.f32.bf16.bf16.f32 " \
                 "{%0,%1,%2,%3}, {%4,%5,%6,%7}, {%8,%9}, {%0,%1,%2,%3};" \
                 : "+f"((d)[0]), "+f"((d)[1]), "+f"((d)[2]), "+f"((d)[3]) \
                 : "r"(a0), "r"(a1), "r"(a2), "r"(a3), "r"(b0), "r"(b1))

// ---------------- prep ----------------
__global__ void prep_cb(const float* __restrict__ cb) {
    int k = blockIdx.x, t = threadIdx.x;
    float v = cb[(size_t)k * NC + t];
    __nv_bfloat16 h = __float2bfloat16_rn(-2.0f * v);
    g_bh[k * NC + t] = *(unsigned short*)&h;
    __shared__ float red[256];
    red[t] = v * v;
    __syncthreads();
    for (int s = 128; s > 0; s >>= 1) { if (t < s) red[t] += red[t + s]; __syncthreads(); }
    if (t == 0) g_cn[k] = red[0];
}

__global__ void prep_z(const float* __restrict__ z) {
    int n = blockIdx.x * blockDim.x + threadIdx.x;
    int b = n >> 10, hw = n & 1023;
    const float* zp = z + (size_t)b * (NC * 1024) + hw;
    float acc = 0.f;
#pragma unroll 8
    for (int c = 0; c < NC; c++) {
        float v = zp[(size_t)c * 1024];
        g_zf[n * NC + c] = v;
        acc += v * v;
        __nv_bfloat16 h = __float2bfloat16_rn(v);
        g_ah[n * NC + c] = *(unsigned short*)&h;
    }
    g_zn[n] = acc;
}

// ---------------- coarse GEMM: 128x128 CTA tile, 8 warps, mma.sync bf16 ----------------
// SMEM: double-buffered A/B k64 slabs. buf b: A @ b*32768, B @ b*32768+16384.
// Epilogue reuses smem to stage bf16 scores for coalesced 16B stores.

__device__ __forceinline__ void issue_loads(uint32_t sb, int buf,
                                            const unsigned short* A, const unsigned short* B,
                                            int kchunk, int t) {
    uint32_t ab = sb + buf * 32768;
    uint32_t bb = ab + 16384;
#pragma unroll
    for (int i = 0; i < 4; i++) {
        int e = i * 256 + t;
        int r = e >> 3, ck = e & 7;
        int sw = (ck * 16) ^ ((r & 7) * 16);
        CP_ASYNC16(ab + r * 128 + sw, A + (size_t)r * NC + kchunk * 64 + ck * 8);
        CP_ASYNC16(bb + r * 128 + sw, B + (size_t)r * NC + kchunk * 64 + ck * 8);
    }
}

__global__ void __launch_bounds__(256) vq_gemm() {
    extern __shared__ char smem[];
    const uint32_t sb = smem_u32(smem);
    const int t = threadIdx.x;
    const int lane = t & 31, wid = t >> 5;
    const int warp_m = wid >> 1, warp_n = wid & 1;   // 4x2 warps -> 32x64 per warp
    const int col0 = blockIdx.x * TN;
    const int row0 = blockIdx.y * TM;
    const unsigned short* A = g_ah + (size_t)row0 * NC;
    const unsigned short* B = g_bh + (size_t)col0 * NC;

    float d[2][8][4];
#pragma unroll
    for (int i = 0; i < 2; i++)
#pragma unroll
        for (int j = 0; j < 8; j++)
#pragma unroll
            for (int q = 0; q < 4; q++) d[i][j][q] = 0.f;

    issue_loads(sb, 0, A, B, 0, t);
    CP_COMMIT();

    for (int kc = 0; kc < 4; kc++) {
        if (kc < 3) {
            issue_loads(sb, (kc + 1) & 1, A, B, kc + 1, t);
            CP_COMMIT();
            CP_WAIT(1);
        } else {
            CP_WAIT(0);
        }
        __syncthreads();

        const uint32_t Ab = sb + (kc & 1) * 32768;
        const uint32_t Bb = Ab + 16384;
#pragma unroll
        for (int ks = 0; ks < 4; ks++) {
            const int c2 = ks * 32 + (lane >> 4) * 16;
            uint32_t a[2][4];
#pragma unroll
            for (int mt = 0; mt < 2; mt++) {
                int row = warp_m * 32 + mt * 16 + (lane & 15);
                uint32_t ad = Ab + row * 128 + (c2 ^ ((row & 7) * 16));
                LDSM_X4(a[mt][0], a[mt][1], a[mt][2], a[mt][3], ad);
            }
            uint32_t bq[4][4];
#pragma unroll
            for (int np = 0; np < 4; np++) {
                int brow = warp_n * 64 + np * 16 + (lane & 15);
                uint32_t bd = Bb + brow * 128 + (c2 ^ ((brow & 7) * 16));
                LDSM_X4(bq[np][0], bq[np][1], bq[np][2], bq[np][3], bd);
            }
#pragma unroll
            for (int mt = 0; mt < 2; mt++)
#pragma unroll
                for (int np = 0; np < 4; np++) {
                    MMA16816(d[mt][np * 2],     a[mt][0], a[mt][1], a[mt][2], a[mt][3],
                             bq[np][0], bq[np][2]);
                    MMA16816(d[mt][np * 2 + 1], a[mt][0], a[mt][1], a[mt][2], a[mt][3],
                             bq[np][1], bq[np][3]);
                }
        }
        __syncthreads();
    }

    // epilogue: +|cb|^2, pack bf16x2, stage in smem (row stride 136 elems), coalesced store
    unsigned short* S = (unsigned short*)smem;
    const int g = lane >> 2, tig = lane & 3;
#pragma unroll
    for (int mt = 0; mt < 2; mt++) {
        const int rbase = warp_m * 32 + mt * 16 + g;
#pragma unroll
        for (int nt = 0; nt < 8; nt++) {
            const int scol = warp_n * 64 + nt * 8 + 2 * tig;
            const float cn0 = __ldg(&g_cn[col0 + scol]);
            const float cn1 = __ldg(&g_cn[col0 + scol + 1]);
#pragma unroll
            for (int half = 0; half < 2; half++) {
                float v0 = d[mt][nt][2 * half + 0] + cn0;
                float v1 = d[mt][nt][2 * half + 1] + cn1;
                uint32_t pk;
                asm("cvt.rn.satfinite.bf16x2.f32 %0, %1, %2;" : "=r"(pk) : "f"(v1), "f"(v0));
                *(uint32_t*)(S + (rbase + half * 8) * 136 + scol) = pk;
            }
        }
    }
    __syncthreads();
#pragma unroll
    for (int i = 0; i < 8; i++) {
        int e = i * 256 + t;
        int r = e >> 4, ch = e & 15;
        uint4 v = *(const uint4*)(S + r * 136 + ch * 8);
        *(uint4*)(g_dist + (size_t)(row0 + r) * NK + col0 + ch * 8) = v;
    }
}

// ---------------- scan + exact fp32 refine ----------------
__global__ void __launch_bounds__(256) vq_scan(const float* __restrict__ cb) {
    const int row = blockIdx.x, t = threadIdx.x;
    const uint4* rp = (const uint4*)(g_dist + (size_t)row * NK);
    uint4 v[4];
#pragma unroll
    for (int i = 0; i < 4; i++) v[i] = rp[t * 4 + i];

    float loc = FLT_MAX;
#pragma unroll
    for (int i = 0; i < 4; i++) {
        const unsigned* u = (const unsigned*)&v[i];
#pragma unroll
        for (int j = 0; j < 4; j++) {
            __nv_bfloat162 p = *(const __nv_bfloat162*)&u[j];
            loc = fminf(loc, fminf(__low2float(p), __high2float(p)));
        }
    }
    __shared__ float sred[256];
    sred[t] = loc;
    __syncthreads();
    for (int s = 128; s > 0; s >>= 1) { if (t < s) sred[t] = fminf(sred[t], sred[t + s]); __syncthreads(); }
    const float thr = sred[0] + MARGIN;
    __syncthreads();

    __shared__ int scnt;
    __shared__ int scand[64];
    if (t == 0) scnt = 0;
    __syncthreads();
#pragma unroll
    for (int i = 0; i < 4; i++) {
        const unsigned* u = (const unsigned*)&v[i];
#pragma unroll
        for (int j = 0; j < 4; j++) {
            __nv_bfloat162 p = *(const __nv_bfloat162*)&u[j];
            float a = __low2float(p), b = __high2float(p);
            int base = t * 32 + i * 8 + j * 2;
            if (a <= thr) { int s0 = atomicAdd(&scnt, 1); if (s0 < 64) scand[s0] = base; }
            if (b <= thr) { int s1 = atomicAdd(&scnt, 1); if (s1 < 64) scand[s1] = base + 1; }
        }
    }
    __syncthreads();
    const int cnt = min(scnt, 64);

    __shared__ float sbv;
    __shared__ int sbi;
    if (t == 0) { sbv = FLT_MAX; sbi = 0x7fffffff; }
    __syncthreads();
    const float zt = g_zf[(size_t)row * NC + t];
    const float zn = g_zn[row];
    for (int c = 0; c < cnt; c++) {
        const int k = scand[c];
        float pv = zt * (-2.0f * cb[(size_t)k * NC + t]);
        sred[t] = pv;
        __syncthreads();
        for (int s = 128; s > 0; s >>= 1) { if (t < s) sred[t] += sred[t + s]; __syncthreads(); }
        if (t == 0) {
            float dd = (sred[0] + zn) + g_cn[k];
            if (dd < sbv || (dd == sbv && k < sbi)) { sbv = dd; sbi = k; }
        }
        __syncthreads();
    }
    if (t == 0) g_idx[row] = sbi;
}

// ---------------- outputs ----------------
__global__ void vq_gather(const float* __restrict__ cb, float* __restrict__ out) {
    int o = blockIdx.x * blockDim.x + threadIdx.x;
    int w = o & 31;
    int h = (o >> 5) & 31;
    int c = (o >> 10) & 255;
    int b = o >> 18;
    int n = (b << 10) + (h << 5) + w;
    out[o] = cb[(size_t)g_idx[n] * NC + c];
}

__global__ void vq_idx_out(float* __restrict__ out) {
    int n = blockIdx.x * blockDim.x + threadIdx.x;
    out[ZQ_ELEMS + n] = (float)g_idx[n];
}

extern "C" void kernel_launch(void* const* d_in, const int* in_sizes, int n_in,
                              void* d_out, int out_size) {
    const float* z  = (const float*)d_in[0];
    const float* cb = (const float*)d_in[1];
    if (n_in >= 2 && in_sizes[0] == NK * NC && in_sizes[1] == NPTS * NC) {
        const float* tmp = z; z = cb; cb = tmp;
    }
    float* out = (float*)d_out;

    cudaFuncSetAttribute(vq_gemm, cudaFuncAttributeMaxDynamicSharedMemorySize, 65536);

    prep_cb<<<NK, 256>>>(cb);
    prep_z<<<NPTS / 256, 256>>>(z);
    vq_gemm<<<dim3(NK / TN, NPTS / TM), 256, 65536>>>();
    vq_scan<<<NPTS, 256>>>(cb);
    vq_gather<<<ZQ_ELEMS / 256, 256>>>(cb, out);
    if (out_size >= ZQ_ELEMS + NPTS)
        vq_idx_out<<<NPTS / 256, 256>>>(out);
}